// round 14
// baseline (speedup 1.0000x reference)
#include <cuda_runtime.h>
#include <cstdint>

#define WW 128
#define HH 128
#define NP 2048
#define DIMU 768
#define PTOT (HH*WW)
#define NBLK 296      // 2 x 148 SMs: exactly 2 CTAs per SM
#define NTHR 256
#define NTILE 256     // 32x2-px raster tiles
#define NCHUNK 512    // 32-px store chunks (x 768 dims)
#define SCAP 512

// ---- device globals (no allocation allowed; reset each run) ----
__device__ __align__(16) float4 g_pA[NP];  // gx, gy, rx, ry (rx<0 => cull)
__device__ __align__(16) float4 g_pB[NP];  // 0.5A, B, 0.5C, op
__device__ __align__(16) float4 g_pC[NP];  // cr, cg, cb, 0
__device__ __align__(16) float g_imr[PTOT], g_img[PTOT], g_imb[PTOT];
__device__ int g_bar1;            // preprocess arrivals
__device__ int g_tile;            // raster ticket
__device__ int g_chunk;           // store ticket
__device__ int g_fin;             // finish counter (last block resets all)
__device__ int g_tflag[NTILE];    // tile-done flags

// ---- packed f32x2 helpers (sm_103a FFMA2) ----
__device__ __forceinline__ unsigned long long pk2(float lo, float hi) {
    unsigned long long v;
    asm("mov.b64 %0, {%1, %2};" : "=l"(v) : "f"(lo), "f"(hi));
    return v;
}
__device__ __forceinline__ unsigned long long ffma2(unsigned long long a,
                                                    unsigned long long b,
                                                    unsigned long long c) {
    unsigned long long d;
    asm("fma.rn.f32x2 %0, %1, %2, %3;" : "=l"(d) : "l"(a), "l"(b), "l"(c));
    return d;
}

__global__ __launch_bounds__(NTHR, 2) void k_one(
    const float* __restrict__ xyz, const float* __restrict__ scaling,
    const float* __restrict__ rotation, const float* __restrict__ features,
    const float* __restrict__ opacity, const float* __restrict__ w_up,
    const float* __restrict__ b_up, float* __restrict__ out)
{
    __shared__ __align__(16) ulonglong2 sw2[DIMU][2]; // {wr2,wg2},{wb2,bias2}
    __shared__ __align__(16) float4 sA[SCAP];
    __shared__ __align__(16) float4 sB[SCAP];
    __shared__ __align__(16) float  scb[SCAP];
    __shared__ __align__(16) float  sar[4][64], sag[4][64], sab[4][64];
    __shared__ int swsum[8];
    __shared__ int s_t, s_c, s_last;

    const int tid  = threadIdx.x;
    const int lane = tid & 31;
    const int wid  = tid >> 5;
    const int bid  = blockIdx.x;

    // ---- A: distributed preprocess (blocks 0..255, 8 gaussians) ----
    if (bid < 256 && tid < 8) {
        const int n = bid * 8 + tid;
        float2 xy = ((const float2*)xyz)[n];
        float2 sc = ((const float2*)scaling)[n];
        float e0 = __expf(2.0f * xy.x);
        float e1 = __expf(2.0f * xy.y);
        float gx = __fdividef(128.0f * e0, e0 + 1.0f);   // 0.5*(tanh+1)*W
        float gy = __fdividef(128.0f * e1, e1 + 1.0f);
        float s0 = fabsf(sc.x + 0.5f);
        float s1 = fabsf(sc.y + 0.5f);
        float th = 6.283185307179586f *
                   __fdividef(1.0f, 1.0f + __expf(-rotation[n]));
        float sn, cs; __sincosf(th, &sn, &cs);
        float a = cs * s0, b = -sn * s1, dd = sn * s0, ee = cs * s1;
        float cxx = a*a + b*b;
        float cxy = a*dd + b*ee;
        float cyy = dd*dd + ee*ee;
        float det = cxx*cyy - cxy*cxy;
        float inv = __fdividef(1.0f, det);
        float hA =  0.5f * cyy * inv;
        float Bc = -cxy * inv;
        float hC =  0.5f * cxx * inv;
        float op = opacity[n];
        float smax = __logf(255.0f * op);   // alpha>=1/255 <=> sigma<=smax
        float rx = -1.0f, ry = -1.0f;
        if (det > 0.0f && smax > 0.0f) {
            rx = sqrtf(2.0f * smax * cxx) * 1.001f + 0.02f;
            ry = sqrtf(2.0f * smax * cyy) * 1.001f + 0.02f;
        }
        g_pA[n] = make_float4(gx, gy, rx, ry);
        g_pB[n] = make_float4(hA, Bc, hC, op);
        g_pC[n] = make_float4(features[3*n+0], features[3*n+1],
                              features[3*n+2], 0.0f);
    }
    __threadfence();
    __syncthreads();
    if (tid == 0) atomicAdd(&g_bar1, 1);

    // ---- B: stage packed weights (overlaps barrier latency) ----
    #pragma unroll
    for (int d = tid; d < DIMU; d += NTHR) {
        float wr = __ldg(&w_up[3*d + 0]);
        float wg = __ldg(&w_up[3*d + 1]);
        float wb = __ldg(&w_up[3*d + 2]);
        float bi = __ldg(&b_up[d]);
        ulonglong2 a; a.x = pk2(wr, wr); a.y = pk2(wg, wg);
        ulonglong2 b; b.x = pk2(wb, wb); b.y = pk2(bi, bi);
        sw2[d][0] = a;
        sw2[d][1] = b;
    }

    // ---- C: grid barrier (all 296 co-resident, no deadlock) ----
    if (tid == 0) {
        while (atomicAdd(&g_bar1, 0) < NBLK) __nanosleep(32);
    }
    __syncthreads();
    __threadfence();

    // ================= D: raster tiles by ticket =================
    while (true) {
        if (tid == 0) s_t = atomicAdd(&g_tile, 1);
        __syncthreads();
        const int t = s_t;
        if (t >= NTILE) break;

        const int x0 = (t & 3) << 5;
        const int y0 = (t >> 2) << 1;
        const float txmin = (float)x0 + 0.5f, txmax = (float)x0 + 31.5f;
        const float tymin = (float)y0 + 0.5f, tymax = (float)y0 + 1.5f;

        // cull: 8 strided gaussians per thread, bitmask + scan
        unsigned keepmask = 0;
        int cnt = 0;
        #pragma unroll
        for (int ck = 0; ck < 8; ck++) {
            float4 pa = g_pA[ck * NTHR + tid];
            bool keep = (pa.z >= 0.0f) &&
                        (pa.x + pa.z >= txmin) && (pa.x - pa.z <= txmax) &&
                        (pa.y + pa.w >= tymin) && (pa.y - pa.w <= tymax);
            keepmask |= keep ? (1u << ck) : 0u;
            cnt += keep ? 1 : 0;
        }
        int inc = cnt;
        #pragma unroll
        for (int d = 1; d < 32; d <<= 1) {
            int v = __shfl_up_sync(0xffffffffu, inc, d);
            inc += (lane >= d) ? v : 0;
        }
        if (lane == 31) swsum[wid] = inc;
        __syncthreads();
        int wbase = 0, total = 0;
        #pragma unroll
        for (int w = 0; w < 8; w++) {
            int cw = swsum[w];
            wbase += (w < wid) ? cw : 0;
            total += cw;
        }
        int off = wbase + inc - cnt;
        #pragma unroll
        for (int ck = 0; ck < 8; ck++) {
            if (keepmask & (1u << ck)) {
                const int n = ck * NTHR + tid;
                float4 pa = g_pA[n];
                float4 pb = g_pB[n];
                float4 pc = g_pC[n];
                if (off < SCAP) {
                    sA[off]  = make_float4(pa.x, pa.y, pb.x, pb.y);
                    sB[off]  = make_float4(pb.z, pb.w, pc.x, pc.y);
                    scb[off] = pc.z;
                }
                off++;
            }
        }
        if (total > SCAP) total = SCAP;
        __syncthreads();

        // sliced raster (4 slices x 64 px)
        const int pix = tid & 63;
        const int slice = tid >> 6;
        const float px = (float)(x0 + (pix & 31)) + 0.5f;
        const float py = (float)(y0 + (pix >> 5)) + 0.5f;
        float accr = 0.0f, accg = 0.0f, accb = 0.0f;
        for (int j = slice; j < total; j += 4) {
            float4 a4 = sA[j];
            float4 b4 = sB[j];
            float  cb = scb[j];
            float dx = a4.x - px;
            float dy = a4.y - py;
            float sig = a4.z * dx * dx + a4.w * dx * dy + b4.x * dy * dy;
            float al = fminf(0.999f, b4.y * __expf(-sig));
            al = (sig >= 0.0f && al >= (1.0f / 255.0f)) ? al : 0.0f;
            accr = fmaf(al, b4.z, accr);
            accg = fmaf(al, b4.w, accg);
            accb = fmaf(al, cb,   accb);
        }
        sar[slice][pix] = accr;
        sag[slice][pix] = accg;
        sab[slice][pix] = accb;
        __syncthreads();
        if (tid < 64) {
            float r = (sar[0][tid] + sar[1][tid]) + (sar[2][tid] + sar[3][tid]);
            float g = (sag[0][tid] + sag[1][tid]) + (sag[2][tid] + sag[3][tid]);
            float b = (sab[0][tid] + sab[1][tid]) + (sab[2][tid] + sab[3][tid]);
            const int p = (y0 + (tid >> 5)) * WW + x0 + (tid & 31);
            g_imr[p] = fminf(1.0f, fmaxf(0.0f, r));
            g_img[p] = fminf(1.0f, fmaxf(0.0f, g));
            g_imb[p] = fminf(1.0f, fmaxf(0.0f, b));
        }
        __threadfence();
        __syncthreads();
        if (tid == 0) atomicExch(&g_tflag[t], 1);   // release tile
    }

    // ================= E: store chunks by ticket =================
    while (true) {
        if (tid == 0) s_c = atomicAdd(&g_chunk, 1);
        __syncthreads();
        const int c = s_c;
        if (c >= NCHUNK) break;
        const int t = (c & 3) | ((c >> 3) << 2);    // owning tile
        if (tid == 0) {
            while (atomicAdd(&g_tflag[t], 0) == 0) __nanosleep(32);
        }
        __syncthreads();
        __threadfence();

        const int pg = tid & 7;                     // float4 group in chunk
        const int dg = tid >> 3;                    // 32 dim-groups x 24 dims
        const int pb = c * 32 + pg * 4;             // pixel base
        float4 R = *(const float4*)&g_imr[pb];
        float4 G = *(const float4*)&g_img[pb];
        float4 B = *(const float4*)&g_imb[pb];
        unsigned long long r01 = pk2(R.x, R.y), r23 = pk2(R.z, R.w);
        unsigned long long g01 = pk2(G.x, G.y), g23 = pk2(G.z, G.w);
        unsigned long long b01 = pk2(B.x, B.y), b23 = pk2(B.z, B.w);

        const int d0 = dg * 24;
        ulonglong2* outp = (ulonglong2*)(out + (size_t)d0 * PTOT + pb);
        #pragma unroll 6
        for (int k = 0; k < 24; k++) {
            ulonglong2 wa = sw2[d0 + k][0];
            ulonglong2 wb = sw2[d0 + k][1];
            ulonglong2 v;
            v.x = ffma2(b01, wb.x, ffma2(g01, wa.y, ffma2(r01, wa.x, wb.y)));
            v.y = ffma2(b23, wb.x, ffma2(g23, wa.y, ffma2(r23, wa.x, wb.y)));
            *outp = v;
            outp += PTOT / 4;
        }
    }

    // ---- F: last block out resets all state (replay-safe) ----
    if (tid == 0) {
        int v = atomicAdd(&g_fin, 1);
        s_last = (v == NBLK - 1) ? 1 : 0;
    }
    __syncthreads();
    if (s_last) {
        if (tid < NTILE) g_tflag[tid] = 0;
        if (tid == 0) { g_bar1 = 0; g_tile = 0; g_chunk = 0; g_fin = 0; }
    }
}

// ============================================================
extern "C" void kernel_launch(void* const* d_in, const int* in_sizes, int n_in,
                              void* d_out, int out_size) {
    // metadata order: x, xyz, scaling, rotation, features, opacity, w_up, b_up
    const float* xyz      = (const float*)d_in[1];
    const float* scaling  = (const float*)d_in[2];
    const float* rotation = (const float*)d_in[3];
    const float* features = (const float*)d_in[4];
    const float* opacity  = (const float*)d_in[5];
    const float* w_up     = (const float*)d_in[6];
    const float* b_up     = (const float*)d_in[7];
    float* out = (float*)d_out;

    k_one<<<NBLK, NTHR>>>(xyz, scaling, rotation, features, opacity,
                          w_up, b_up, out);
}

// round 15
// speedup vs baseline: 1.0985x; 1.0985x over previous
#include <cuda_runtime.h>
#include <cstdint>

#define WW 128
#define HH 128
#define NP 2048
#define DIMU 768
#define PTOT (HH*WW)
#define NBLK 256
#define NTHR 256
#define SCAP 512      // survivor capacity per 32x2 tile (expect ~65)

// ---- device globals (no allocation allowed) ----
__device__ __align__(16) float4 g_pA[NP];  // gx, gy, rx, ry (rx<0 => cull)
__device__ __align__(16) float4 g_pB[NP];  // 0.5A, B, 0.5C, op
__device__ __align__(16) float4 g_pC[NP];  // cr, cg, cb, 0
__device__ int g_bar1;   // produce-arrivals (0..256)
__device__ int g_bar2;   // pass-arrivals, last resets both

// ---- packed f32x2 helpers (sm_103a FFMA2) ----
__device__ __forceinline__ unsigned long long pk2(float lo, float hi) {
    unsigned long long v;
    asm("mov.b64 %0, {%1, %2};" : "=l"(v) : "f"(lo), "f"(hi));
    return v;
}
__device__ __forceinline__ unsigned long long ffma2(unsigned long long a,
                                                    unsigned long long b,
                                                    unsigned long long c) {
    unsigned long long d;
    asm("fma.rn.f32x2 %0, %1, %2, %3;" : "=l"(d) : "l"(a), "l"(b), "l"(c));
    return d;
}
#define BAR_SYNC(id, cnt) \
    asm volatile("bar.sync %0, %1;" :: "r"(id), "r"(cnt) : "memory")
#define BAR_ARRIVE(id, cnt) \
    asm volatile("bar.arrive %0, %1;" :: "r"(id), "r"(cnt) : "memory")

// ============================================================
// Single kernel, 256 blocks x 256 threads, warp-specialized.
// Block = one 32x2-px tile.
//  A) block b preprocesses gaussians [8b,8b+8) ONCE -> global
//  B) grid barrier (proven replay-safe counter pattern)
//  producers (warps 0-3): cull+compact, raster row 0, signal,
//                         raster row 1, signal
//  consumers (warps 4-7): stage weights, per row: wait + project
//                         48 dims/thread via f32x2 + STG.128
//  -> the SM's LSU drains row-0 stores while FMA rasters row 1.
// ============================================================
__global__ __launch_bounds__(NTHR, 2) void k_one(
    const float* __restrict__ xyz, const float* __restrict__ scaling,
    const float* __restrict__ rotation, const float* __restrict__ features,
    const float* __restrict__ opacity, const float* __restrict__ w_up,
    const float* __restrict__ b_up, float* __restrict__ out)
{
    __shared__ __align__(16) ulonglong2 sw2[DIMU][2]; // {wr2,wg2},{wb2,bias2}
    __shared__ __align__(16) float4 sA[SCAP];         // gx, gy, 0.5A, B
    __shared__ __align__(16) float4 sB[SCAP];         // 0.5C, op, cr, cg
    __shared__ __align__(16) float  scb[SCAP];        // cb
    __shared__ __align__(16) float  sar[4][32], sag[4][32], sab[4][32];
    __shared__ __align__(16) float  spr[2][32], spg[2][32], spb[2][32];
    __shared__ int swsum[4];
    __shared__ int s_total;

    const int tid  = threadIdx.x;
    const int lane = tid & 31;
    const int wid  = tid >> 5;
    const int bid  = blockIdx.x;

    // ---- A: distributed preprocess (8 gaussians per block) ----
    if (tid < 8) {
        const int n = bid * 8 + tid;
        float2 xy = ((const float2*)xyz)[n];
        float2 sc = ((const float2*)scaling)[n];
        float e0 = __expf(2.0f * xy.x);
        float e1 = __expf(2.0f * xy.y);
        float gx = __fdividef(128.0f * e0, e0 + 1.0f);   // 0.5*(tanh+1)*W
        float gy = __fdividef(128.0f * e1, e1 + 1.0f);
        float s0 = fabsf(sc.x + 0.5f);
        float s1 = fabsf(sc.y + 0.5f);
        float th = 6.283185307179586f *
                   __fdividef(1.0f, 1.0f + __expf(-rotation[n]));
        float sn, cs; __sincosf(th, &sn, &cs);
        float a = cs * s0, b = -sn * s1, dd = sn * s0, ee = cs * s1;
        float cxx = a*a + b*b;
        float cxy = a*dd + b*ee;
        float cyy = dd*dd + ee*ee;
        float det = cxx*cyy - cxy*cxy;
        float inv = __fdividef(1.0f, det);
        float hA =  0.5f * cyy * inv;
        float Bc = -cxy * inv;
        float hC =  0.5f * cxx * inv;
        float op = opacity[n];
        float smax = __logf(255.0f * op);   // alpha>=1/255 <=> sigma<=smax
        float rx = -1.0f, ry = -1.0f;
        if (det > 0.0f && smax > 0.0f) {
            rx = sqrtf(2.0f * smax * cxx) * 1.001f + 0.02f;
            ry = sqrtf(2.0f * smax * cyy) * 1.001f + 0.02f;
        }
        g_pA[n] = make_float4(gx, gy, rx, ry);
        g_pB[n] = make_float4(hA, Bc, hC, op);
        g_pC[n] = make_float4(features[3*n+0], features[3*n+1],
                              features[3*n+2], 0.0f);
    }
    __threadfence();
    __syncthreads();
    if (tid == 0) atomicAdd(&g_bar1, 1);

    // consumers stage packed weights (overlaps the barrier wait)
    if (tid >= 128) {
        #pragma unroll
        for (int d = tid - 128; d < DIMU; d += 128) {
            float wr = __ldg(&w_up[3*d + 0]);
            float wg = __ldg(&w_up[3*d + 1]);
            float wb = __ldg(&w_up[3*d + 2]);
            float bi = __ldg(&b_up[d]);
            ulonglong2 a; a.x = pk2(wr, wr); a.y = pk2(wg, wg);
            ulonglong2 b; b.x = pk2(wb, wb); b.y = pk2(bi, bi);
            sw2[d][0] = a;
            sw2[d][1] = b;
        }
    }

    // ---- B: grid barrier (all 256 co-resident at occ 2) ----
    if (tid == 0) {
        while (atomicAdd(&g_bar1, 0) < NBLK) __nanosleep(32);
        int v = atomicAdd(&g_bar2, 1);
        if (v == NBLK - 1) { g_bar2 = 0; g_bar1 = 0; }  // replay-safe reset
    }
    __syncthreads();
    __threadfence();

    // ---- tile geometry: 32x2 px ----
    const int x0 = (bid & 3) << 5;        // 0,32,64,96
    const int y0 = (bid >> 2) << 1;       // 0..126 step 2

    if (tid < 128) {
        // =================== PRODUCERS (warps 0-3) ===================
        const float txmin = (float)x0 + 0.5f, txmax = (float)x0 + 31.5f;
        const float tymin = (float)y0 + 0.5f, tymax = (float)y0 + 1.5f;

        // cull: 16 strided gaussians per thread, bitmask + scan
        unsigned keepmask = 0;
        int cnt = 0;
        #pragma unroll
        for (int ck = 0; ck < 16; ck++) {
            float4 pa = g_pA[ck * 128 + tid];
            bool keep = (pa.z >= 0.0f) &&
                        (pa.x + pa.z >= txmin) && (pa.x - pa.z <= txmax) &&
                        (pa.y + pa.w >= tymin) && (pa.y - pa.w <= tymax);
            keepmask |= keep ? (1u << ck) : 0u;
            cnt += keep ? 1 : 0;
        }
        int inc = cnt;
        #pragma unroll
        for (int d = 1; d < 32; d <<= 1) {
            int t = __shfl_up_sync(0xffffffffu, inc, d);
            inc += (lane >= d) ? t : 0;
        }
        if (lane == 31) swsum[wid] = inc;
        BAR_SYNC(1, 128);
        int wbase = 0, total = 0;
        #pragma unroll
        for (int w = 0; w < 4; w++) {
            int cw = swsum[w];
            wbase += (w < wid) ? cw : 0;
            total += cw;
        }
        int off = wbase + inc - cnt;
        #pragma unroll
        for (int ck = 0; ck < 16; ck++) {
            if (keepmask & (1u << ck)) {
                const int n = ck * 128 + tid;
                float4 pa = g_pA[n];
                float4 pb = g_pB[n];
                float4 pc = g_pC[n];
                if (off < SCAP) {
                    sA[off]  = make_float4(pa.x, pa.y, pb.x, pb.y);
                    sB[off]  = make_float4(pb.z, pb.w, pc.x, pc.y);
                    scb[off] = pc.z;
                }
                off++;
            }
        }
        if (total > SCAP) total = SCAP;
        BAR_SYNC(1, 128);

        // raster row-by-row: 32 px x 4 slices
        const int pix = tid & 31;
        const int slice = tid >> 5;       // 0..3
        const float px = (float)(x0 + pix) + 0.5f;
        #pragma unroll 1
        for (int s = 0; s < 2; s++) {
            const float py = (float)(y0 + s) + 0.5f;
            float accr = 0.0f, accg = 0.0f, accb = 0.0f;
            for (int j = slice; j < total; j += 4) {
                float4 a4 = sA[j];
                float4 b4 = sB[j];
                float  cb = scb[j];
                float dx = a4.x - px;
                float dy = a4.y - py;
                float sig = a4.z * dx * dx + a4.w * dx * dy + b4.x * dy * dy;
                float al = fminf(0.999f, b4.y * __expf(-sig));
                al = (sig >= 0.0f && al >= (1.0f / 255.0f)) ? al : 0.0f;
                accr = fmaf(al, b4.z, accr);
                accg = fmaf(al, b4.w, accg);
                accb = fmaf(al, cb,   accb);
            }
            sar[slice][pix] = accr;
            sag[slice][pix] = accg;
            sab[slice][pix] = accb;
            BAR_SYNC(1, 128);
            if (tid < 32) {
                float r = (sar[0][tid] + sar[1][tid]) + (sar[2][tid] + sar[3][tid]);
                float g = (sag[0][tid] + sag[1][tid]) + (sag[2][tid] + sag[3][tid]);
                float b = (sab[0][tid] + sab[1][tid]) + (sab[2][tid] + sab[3][tid]);
                spr[s][tid] = fminf(1.0f, fmaxf(0.0f, r));
                spg[s][tid] = fminf(1.0f, fmaxf(0.0f, g));
                spb[s][tid] = fminf(1.0f, fmaxf(0.0f, b));
            }
            BAR_SYNC(1, 128);             // spr visible to all producers
            BAR_ARRIVE(4 + s, 256);       // release row s to consumers
        }
    } else {
        // =================== CONSUMERS (warps 4-7) ===================
        const int t2 = tid - 128;
        const int pg = t2 & 7;            // float4 group within the row
        const int dg = t2 >> 3;           // 16 dim groups x 48 dims
        const int d0 = dg * 48;

        #pragma unroll 1
        for (int s = 0; s < 2; s++) {
            BAR_SYNC(4 + s, 256);         // wait for row s
            float4 R = ((const float4*)spr[s])[pg];
            float4 G = ((const float4*)spg[s])[pg];
            float4 B = ((const float4*)spb[s])[pg];
            unsigned long long r01 = pk2(R.x, R.y), r23 = pk2(R.z, R.w);
            unsigned long long g01 = pk2(G.x, G.y), g23 = pk2(G.z, G.w);
            unsigned long long b01 = pk2(B.x, B.y), b23 = pk2(B.z, B.w);

            ulonglong2* outp = (ulonglong2*)(out + (size_t)d0 * PTOT
                                                 + (size_t)(y0 + s) * WW + x0) + pg;
            #pragma unroll 6
            for (int k = 0; k < 48; k++) {
                ulonglong2 wa = sw2[d0 + k][0];   // {wr2, wg2}
                ulonglong2 wb = sw2[d0 + k][1];   // {wb2, bias2}
                ulonglong2 v;
                v.x = ffma2(b01, wb.x, ffma2(g01, wa.y, ffma2(r01, wa.x, wb.y)));
                v.y = ffma2(b23, wb.x, ffma2(g23, wa.y, ffma2(r23, wa.x, wb.y)));
                *outp = v;
                outp += PTOT / 4;                 // next dim
            }
        }
    }
}

// ============================================================
extern "C" void kernel_launch(void* const* d_in, const int* in_sizes, int n_in,
                              void* d_out, int out_size) {
    // metadata order: x, xyz, scaling, rotation, features, opacity, w_up, b_up
    const float* xyz      = (const float*)d_in[1];
    const float* scaling  = (const float*)d_in[2];
    const float* rotation = (const float*)d_in[3];
    const float* features = (const float*)d_in[4];
    const float* opacity  = (const float*)d_in[5];
    const float* w_up     = (const float*)d_in[6];
    const float* b_up     = (const float*)d_in[7];
    float* out = (float*)d_out;

    k_one<<<NBLK, NTHR>>>(xyz, scaling, rotation, features, opacity,
                          w_up, b_up, out);
}

// round 16
// speedup vs baseline: 1.1153x; 1.0153x over previous
#include <cuda_runtime.h>
#include <cstdint>

#define WW 128
#define HH 128
#define NP 2048
#define DIMU 768
#define PTOT (HH*WW)
#define NBLK 256
#define NTHR 256
#define SCAP 512      // survivor capacity per 32x2 tile (expect ~65)

// ---- device globals (no allocation allowed) ----
__device__ __align__(16) float4 g_pA[NP];  // gx, gy, rx, ry (rx<0 => cull)
__device__ __align__(16) float4 g_pB[NP];  // 0.5A, B, 0.5C, op
__device__ __align__(16) float4 g_pC[NP];  // cr, cg, cb, 0
__device__ int g_bar1;    // produce-arrivals (0..256)
__device__ int g_ready;   // flag set by 256th arriver (polled by loads)
__device__ int g_bar2;    // exit-arrivals, last resets all

// ---- packed f32x2 helpers (sm_103a FFMA2) ----
__device__ __forceinline__ unsigned long long pk2(float lo, float hi) {
    unsigned long long v;
    asm("mov.b64 %0, {%1, %2};" : "=l"(v) : "f"(lo), "f"(hi));
    return v;
}
__device__ __forceinline__ unsigned long long ffma2(unsigned long long a,
                                                    unsigned long long b,
                                                    unsigned long long c) {
    unsigned long long d;
    asm("fma.rn.f32x2 %0, %1, %2, %3;" : "=l"(d) : "l"(a), "l"(b), "l"(c));
    return d;
}

// ============================================================
// Single kernel, 256 blocks x 256 threads, all co-resident
// (occ 2 -> capacity 296 >= 256: flag barrier is safe).
// Block = one 32x2-px tile. R13 structure; barrier rebuilt as
// count-then-flag: waiters poll a plain int with volatile loads
// (L2 line broadcast) instead of atomicAdd RMWs that serialize
// in the LTS atomic ALU.
// ============================================================
__global__ __launch_bounds__(NTHR, 2) void k_one(
    const float* __restrict__ xyz, const float* __restrict__ scaling,
    const float* __restrict__ rotation, const float* __restrict__ features,
    const float* __restrict__ opacity, const float* __restrict__ w_up,
    const float* __restrict__ b_up, float* __restrict__ out)
{
    __shared__ __align__(16) ulonglong2 sw2[DIMU][2]; // {wr2,wg2},{wb2,bias2}
    __shared__ __align__(16) float4 sA[SCAP];         // gx, gy, 0.5A, B
    __shared__ __align__(16) float4 sB[SCAP];         // 0.5C, op, cr, cg
    __shared__ __align__(16) float  scb[SCAP];        // cb
    __shared__ __align__(16) float  sar[4][64], sag[4][64], sab[4][64];
    __shared__ __align__(16) float  spr[64], spg[64], spb[64];
    __shared__ int swsum[8];

    const int tid  = threadIdx.x;
    const int lane = tid & 31;
    const int wid  = tid >> 5;
    const int bid  = blockIdx.x;

    // ---- A: distributed preprocess (8 gaussians per block) ----
    if (tid < 8) {
        const int n = bid * 8 + tid;
        float2 xy = ((const float2*)xyz)[n];
        float2 sc = ((const float2*)scaling)[n];
        float e0 = __expf(2.0f * xy.x);
        float e1 = __expf(2.0f * xy.y);
        float gx = __fdividef(128.0f * e0, e0 + 1.0f);   // 0.5*(tanh+1)*W
        float gy = __fdividef(128.0f * e1, e1 + 1.0f);
        float s0 = fabsf(sc.x + 0.5f);
        float s1 = fabsf(sc.y + 0.5f);
        float th = 6.283185307179586f *
                   __fdividef(1.0f, 1.0f + __expf(-rotation[n]));
        float sn, cs; __sincosf(th, &sn, &cs);
        float a = cs * s0, b = -sn * s1, dd = sn * s0, ee = cs * s1;
        float cxx = a*a + b*b;
        float cxy = a*dd + b*ee;
        float cyy = dd*dd + ee*ee;
        float det = cxx*cyy - cxy*cxy;
        float inv = __fdividef(1.0f, det);
        float hA =  0.5f * cyy * inv;
        float Bc = -cxy * inv;
        float hC =  0.5f * cxx * inv;
        float op = opacity[n];
        float smax = __logf(255.0f * op);   // alpha>=1/255 <=> sigma<=smax
        float rx = -1.0f, ry = -1.0f;
        if (det > 0.0f && smax > 0.0f) {
            rx = sqrtf(2.0f * smax * cxx) * 1.001f + 0.02f;
            ry = sqrtf(2.0f * smax * cyy) * 1.001f + 0.02f;
        }
        g_pA[n] = make_float4(gx, gy, rx, ry);
        g_pB[n] = make_float4(hA, Bc, hC, op);
        g_pC[n] = make_float4(features[3*n+0], features[3*n+1],
                              features[3*n+2], 0.0f);
    }
    __threadfence();
    __syncthreads();
    if (tid == 0) {
        int v = atomicAdd(&g_bar1, 1);
        if (v == NBLK - 1) {
            __threadfence();
            *((volatile int*)&g_ready) = 1;   // release flag
        }
    }

    // ---- B: stage packed weights (overlaps barrier latency) ----
    #pragma unroll
    for (int d = tid; d < DIMU; d += NTHR) {
        float wr = __ldg(&w_up[3*d + 0]);
        float wg = __ldg(&w_up[3*d + 1]);
        float wb = __ldg(&w_up[3*d + 2]);
        float bi = __ldg(&b_up[d]);
        ulonglong2 a; a.x = pk2(wr, wr); a.y = pk2(wg, wg);
        ulonglong2 b; b.x = pk2(wb, wb); b.y = pk2(bi, bi);
        sw2[d][0] = a;
        sw2[d][1] = b;
    }

    // ---- C: flag barrier (volatile-load polling, no RMW storm) ----
    if (tid == 0) {
        while (*((volatile int*)&g_ready) == 0) __nanosleep(32);
        int v = atomicAdd(&g_bar2, 1);
        if (v == NBLK - 1) { g_bar2 = 0; g_bar1 = 0; g_ready = 0; } // reset
    }
    __syncthreads();
    __threadfence();   // acquire: order param reads after flag observation

    // ---- tile geometry: 32x2 px ----
    const int x0 = (bid & 3) << 5;        // 0,32,64,96
    const int y0 = (bid >> 2) << 1;       // 0..126 step 2
    const float txmin = (float)x0 + 0.5f, txmax = (float)x0 + 31.5f;
    const float tymin = (float)y0 + 0.5f, tymax = (float)y0 + 1.5f;

    // ---- D1: cull pass (8 strided gaussians per thread) ----
    unsigned keepmask = 0;
    int cnt = 0;
    #pragma unroll
    for (int ck = 0; ck < 8; ck++) {
        float4 pa = g_pA[ck * NTHR + tid];
        bool keep = (pa.z >= 0.0f) &&
                    (pa.x + pa.z >= txmin) && (pa.x - pa.z <= txmax) &&
                    (pa.y + pa.w >= tymin) && (pa.y - pa.w <= tymax);
        keepmask |= keep ? (1u << ck) : 0u;
        cnt += keep ? 1 : 0;
    }

    // block prefix-scan of counts (deterministic thread-major order)
    int inc = cnt;
    #pragma unroll
    for (int d = 1; d < 32; d <<= 1) {
        int t = __shfl_up_sync(0xffffffffu, inc, d);
        inc += (lane >= d) ? t : 0;
    }
    if (lane == 31) swsum[wid] = inc;
    __syncthreads();
    int wbase = 0, total = 0;
    #pragma unroll
    for (int w = 0; w < 8; w++) {
        int cw = swsum[w];
        wbase += (w < wid) ? cw : 0;
        total += cw;
    }
    int off = wbase + inc - cnt;          // exclusive prefix

    // ---- D2: compact survivors (reloads are L1-hot) ----
    #pragma unroll
    for (int ck = 0; ck < 8; ck++) {
        if (keepmask & (1u << ck)) {
            const int n = ck * NTHR + tid;
            float4 pa = g_pA[n];
            float4 pb = g_pB[n];
            float4 pc = g_pC[n];
            if (off < SCAP) {
                sA[off]  = make_float4(pa.x, pa.y, pb.x, pb.y);
                sB[off]  = make_float4(pb.z, pb.w, pc.x, pc.y);
                scb[off] = pc.z;
            }
            off++;
        }
    }
    if (total > SCAP) total = SCAP;
    __syncthreads();

    // ---- E: sliced raster (4 slices, 2 warps each) ----
    const int pix = tid & 63;             // pixel 0..63
    const int slice = tid >> 6;           // 0..3
    const float px = (float)(x0 + (pix & 31)) + 0.5f;
    const float py = (float)(y0 + (pix >> 5)) + 0.5f;
    float accr = 0.0f, accg = 0.0f, accb = 0.0f;
    for (int j = slice; j < total; j += 4) {
        float4 a4 = sA[j];
        float4 b4 = sB[j];
        float  cb = scb[j];
        float dx = a4.x - px;
        float dy = a4.y - py;
        float sig = a4.z * dx * dx + a4.w * dx * dy + b4.x * dy * dy;
        float al = fminf(0.999f, b4.y * __expf(-sig));
        al = (sig >= 0.0f && al >= (1.0f / 255.0f)) ? al : 0.0f;
        accr = fmaf(al, b4.z, accr);
        accg = fmaf(al, b4.w, accg);
        accb = fmaf(al, cb,   accb);
    }
    sar[slice][pix] = accr;
    sag[slice][pix] = accg;
    sab[slice][pix] = accb;
    __syncthreads();
    if (tid < 64) {
        float r = (sar[0][tid] + sar[1][tid]) + (sar[2][tid] + sar[3][tid]);
        float g = (sag[0][tid] + sag[1][tid]) + (sag[2][tid] + sag[3][tid]);
        float b = (sab[0][tid] + sab[1][tid]) + (sab[2][tid] + sab[3][tid]);
        spr[tid] = fminf(1.0f, fmaxf(0.0f, r));
        spg[tid] = fminf(1.0f, fmaxf(0.0f, g));
        spb[tid] = fminf(1.0f, fmaxf(0.0f, b));
    }
    __syncthreads();

    // ---- F: projection + coalesced stores ----
    const int pg = tid & 15;              // float4 pixel group (16 x 4px)
    const int dg = tid >> 4;              // 16 dim groups x 48 dims
    const int prow = pg >> 3;
    const int pcol = pg & 7;

    float4 R = ((const float4*)spr)[pg];
    float4 G = ((const float4*)spg)[pg];
    float4 B = ((const float4*)spb)[pg];
    unsigned long long r01 = pk2(R.x, R.y), r23 = pk2(R.z, R.w);
    unsigned long long g01 = pk2(G.x, G.y), g23 = pk2(G.z, G.w);
    unsigned long long b01 = pk2(B.x, B.y), b23 = pk2(B.z, B.w);

    const int d0 = dg * 48;
    ulonglong2* outp = (ulonglong2*)(out + (size_t)d0 * PTOT
                                         + (size_t)(y0 + prow) * WW + x0) + pcol;

    #pragma unroll 8
    for (int k = 0; k < 48; k++) {
        ulonglong2 wa = sw2[d0 + k][0];   // {wr2, wg2}
        ulonglong2 wb = sw2[d0 + k][1];   // {wb2, bias2}
        ulonglong2 v;
        v.x = ffma2(b01, wb.x, ffma2(g01, wa.y, ffma2(r01, wa.x, wb.y)));
        v.y = ffma2(b23, wb.x, ffma2(g23, wa.y, ffma2(r23, wa.x, wb.y)));
        *outp = v;
        outp += PTOT / 4;                 // next dim (PTOT floats)
    }
}

// ============================================================
extern "C" void kernel_launch(void* const* d_in, const int* in_sizes, int n_in,
                              void* d_out, int out_size) {
    // metadata order: x, xyz, scaling, rotation, features, opacity, w_up, b_up
    const float* xyz      = (const float*)d_in[1];
    const float* scaling  = (const float*)d_in[2];
    const float* rotation = (const float*)d_in[3];
    const float* features = (const float*)d_in[4];
    const float* opacity  = (const float*)d_in[5];
    const float* w_up     = (const float*)d_in[6];
    const float* b_up     = (const float*)d_in[7];
    float* out = (float*)d_out;

    k_one<<<NBLK, NTHR>>>(xyz, scaling, rotation, features, opacity,
                          w_up, b_up, out);
}

// round 17
// speedup vs baseline: 1.1190x; 1.0034x over previous
#include <cuda_runtime.h>
#include <cstdint>

#define WW 128
#define HH 128
#define NP 2048
#define DIMU 768
#define PTOT (HH*WW)
#define NBLK 128
#define NTHR 512
#define SCAP 512      // survivor capacity per 32x4 tile (expect ~70)

// ---- device globals (no allocation allowed) ----
__device__ __align__(16) float4 g_pA[NP];  // gx, gy, rx, ry (rx<0 => cull)
__device__ __align__(16) float4 g_pB[NP];  // 0.5A, B, 0.5C, op
__device__ __align__(16) float4 g_pC[NP];  // cr, cg, cb, 0
__device__ int g_bar1;    // produce-arrivals (0..128)
__device__ int g_ready;   // flag set by last arriver
__device__ int g_bar2;    // exit-arrivals, last resets all

// ---- packed f32x2 helpers (sm_103a FFMA2) ----
__device__ __forceinline__ unsigned long long pk2(float lo, float hi) {
    unsigned long long v;
    asm("mov.b64 %0, {%1, %2};" : "=l"(v) : "f"(lo), "f"(hi));
    return v;
}
__device__ __forceinline__ unsigned long long ffma2(unsigned long long a,
                                                    unsigned long long b,
                                                    unsigned long long c) {
    unsigned long long d;
    asm("fma.rn.f32x2 %0, %1, %2, %3;" : "=l"(d) : "l"(a), "l"(b), "l"(c));
    return d;
}

// ============================================================
// Single kernel, 128 blocks x 512 threads -> 32 warps/SM
// (2 CTA/SM, 1024 threads/SM: doubles latency-hiding vs all
// previous 16-warp/SM shapes). Block = one 32x4-px tile.
//  A) block b preprocesses gaussians [16b,16b+16) ONCE -> global
//  B) stage 768 packed weights -> smem (overlaps barrier)
//  C) count-then-flag grid barrier (replay-safe)
//  D) cull 4 strided/thread, bitmask + block scan compact
//  E) raster 128 px x 4 slices, fixed-order reduce
//  F) project 48 dims/thread, coalesced STG.128
// ============================================================
__global__ __launch_bounds__(NTHR, 2) void k_one(
    const float* __restrict__ xyz, const float* __restrict__ scaling,
    const float* __restrict__ rotation, const float* __restrict__ features,
    const float* __restrict__ opacity, const float* __restrict__ w_up,
    const float* __restrict__ b_up, float* __restrict__ out)
{
    __shared__ __align__(16) ulonglong2 sw2[DIMU][2]; // {wr2,wg2},{wb2,bias2}
    __shared__ __align__(16) float4 sA[SCAP];         // gx, gy, 0.5A, B
    __shared__ __align__(16) float4 sB[SCAP];         // 0.5C, op, cr, cg
    __shared__ __align__(16) float  scb[SCAP];        // cb
    __shared__ __align__(16) float  sar[4][128], sag[4][128], sab[4][128];
    __shared__ __align__(16) float  spr[128], spg[128], spb[128];
    __shared__ int swsum[16];

    const int tid  = threadIdx.x;
    const int lane = tid & 31;
    const int wid  = tid >> 5;
    const int bid  = blockIdx.x;

    // ---- A: distributed preprocess (16 gaussians per block) ----
    if (tid < 16) {
        const int n = bid * 16 + tid;
        float2 xy = ((const float2*)xyz)[n];
        float2 sc = ((const float2*)scaling)[n];
        float e0 = __expf(2.0f * xy.x);
        float e1 = __expf(2.0f * xy.y);
        float gx = __fdividef(128.0f * e0, e0 + 1.0f);   // 0.5*(tanh+1)*W
        float gy = __fdividef(128.0f * e1, e1 + 1.0f);
        float s0 = fabsf(sc.x + 0.5f);
        float s1 = fabsf(sc.y + 0.5f);
        float th = 6.283185307179586f *
                   __fdividef(1.0f, 1.0f + __expf(-rotation[n]));
        float sn, cs; __sincosf(th, &sn, &cs);
        float a = cs * s0, b = -sn * s1, dd = sn * s0, ee = cs * s1;
        float cxx = a*a + b*b;
        float cxy = a*dd + b*ee;
        float cyy = dd*dd + ee*ee;
        float det = cxx*cyy - cxy*cxy;
        float inv = __fdividef(1.0f, det);
        float hA =  0.5f * cyy * inv;
        float Bc = -cxy * inv;
        float hC =  0.5f * cxx * inv;
        float op = opacity[n];
        float smax = __logf(255.0f * op);   // alpha>=1/255 <=> sigma<=smax
        float rx = -1.0f, ry = -1.0f;
        if (det > 0.0f && smax > 0.0f) {
            rx = sqrtf(2.0f * smax * cxx) * 1.001f + 0.02f;
            ry = sqrtf(2.0f * smax * cyy) * 1.001f + 0.02f;
        }
        g_pA[n] = make_float4(gx, gy, rx, ry);
        g_pB[n] = make_float4(hA, Bc, hC, op);
        g_pC[n] = make_float4(features[3*n+0], features[3*n+1],
                              features[3*n+2], 0.0f);
    }
    __threadfence();
    __syncthreads();
    if (tid == 0) {
        int v = atomicAdd(&g_bar1, 1);
        if (v == NBLK - 1) {
            __threadfence();
            *((volatile int*)&g_ready) = 1;   // release flag
        }
    }

    // ---- B: stage packed weights (overlaps barrier latency) ----
    #pragma unroll
    for (int d = tid; d < DIMU; d += NTHR) {
        float wr = __ldg(&w_up[3*d + 0]);
        float wg = __ldg(&w_up[3*d + 1]);
        float wb = __ldg(&w_up[3*d + 2]);
        float bi = __ldg(&b_up[d]);
        ulonglong2 a; a.x = pk2(wr, wr); a.y = pk2(wg, wg);
        ulonglong2 b; b.x = pk2(wb, wb); b.y = pk2(bi, bi);
        sw2[d][0] = a;
        sw2[d][1] = b;
    }

    // ---- C: flag barrier (volatile-load polling) ----
    if (tid == 0) {
        while (*((volatile int*)&g_ready) == 0) __nanosleep(32);
        int v = atomicAdd(&g_bar2, 1);
        if (v == NBLK - 1) { g_bar2 = 0; g_bar1 = 0; g_ready = 0; } // reset
    }
    __syncthreads();
    __threadfence();   // acquire

    // ---- tile geometry: 32x4 px ----
    const int x0 = (bid & 3) << 5;        // 0,32,64,96
    const int y0 = (bid >> 2) << 2;       // 0..124 step 4
    const float txmin = (float)x0 + 0.5f, txmax = (float)x0 + 31.5f;
    const float tymin = (float)y0 + 0.5f, tymax = (float)y0 + 3.5f;

    // ---- D1: cull pass (4 strided gaussians per thread) ----
    unsigned keepmask = 0;
    int cnt = 0;
    #pragma unroll
    for (int ck = 0; ck < 4; ck++) {
        float4 pa = g_pA[ck * NTHR + tid];
        bool keep = (pa.z >= 0.0f) &&
                    (pa.x + pa.z >= txmin) && (pa.x - pa.z <= txmax) &&
                    (pa.y + pa.w >= tymin) && (pa.y - pa.w <= tymax);
        keepmask |= keep ? (1u << ck) : 0u;
        cnt += keep ? 1 : 0;
    }

    // block prefix-scan of counts (deterministic thread-major order)
    int inc = cnt;
    #pragma unroll
    for (int d = 1; d < 32; d <<= 1) {
        int t = __shfl_up_sync(0xffffffffu, inc, d);
        inc += (lane >= d) ? t : 0;
    }
    if (lane == 31) swsum[wid] = inc;
    __syncthreads();
    int wbase = 0, total = 0;
    #pragma unroll
    for (int w = 0; w < 16; w++) {
        int cw = swsum[w];
        wbase += (w < wid) ? cw : 0;
        total += cw;
    }
    int off = wbase + inc - cnt;          // exclusive prefix

    // ---- D2: compact survivors (reloads are L1-hot) ----
    #pragma unroll
    for (int ck = 0; ck < 4; ck++) {
        if (keepmask & (1u << ck)) {
            const int n = ck * NTHR + tid;
            float4 pa = g_pA[n];
            float4 pb = g_pB[n];
            float4 pc = g_pC[n];
            if (off < SCAP) {
                sA[off]  = make_float4(pa.x, pa.y, pb.x, pb.y);
                sB[off]  = make_float4(pb.z, pb.w, pc.x, pc.y);
                scb[off] = pc.z;
            }
            off++;
        }
    }
    if (total > SCAP) total = SCAP;
    __syncthreads();

    // ---- E: sliced raster (4 slices x 128 px) ----
    const int pix = tid & 127;            // pixel 0..127
    const int slice = tid >> 7;           // 0..3
    const float px = (float)(x0 + (pix & 31)) + 0.5f;
    const float py = (float)(y0 + (pix >> 5)) + 0.5f;
    float accr = 0.0f, accg = 0.0f, accb = 0.0f;
    for (int j = slice; j < total; j += 4) {
        float4 a4 = sA[j];
        float4 b4 = sB[j];
        float  cb = scb[j];
        float dx = a4.x - px;
        float dy = a4.y - py;
        float sig = a4.z * dx * dx + a4.w * dx * dy + b4.x * dy * dy;
        float al = fminf(0.999f, b4.y * __expf(-sig));
        al = (sig >= 0.0f && al >= (1.0f / 255.0f)) ? al : 0.0f;
        accr = fmaf(al, b4.z, accr);
        accg = fmaf(al, b4.w, accg);
        accb = fmaf(al, cb,   accb);
    }
    sar[slice][pix] = accr;
    sag[slice][pix] = accg;
    sab[slice][pix] = accb;
    __syncthreads();
    if (tid < 128) {
        float r = (sar[0][tid] + sar[1][tid]) + (sar[2][tid] + sar[3][tid]);
        float g = (sag[0][tid] + sag[1][tid]) + (sag[2][tid] + sag[3][tid]);
        float b = (sab[0][tid] + sab[1][tid]) + (sab[2][tid] + sab[3][tid]);
        spr[tid] = fminf(1.0f, fmaxf(0.0f, r));
        spg[tid] = fminf(1.0f, fmaxf(0.0f, g));
        spb[tid] = fminf(1.0f, fmaxf(0.0f, b));
    }
    __syncthreads();

    // ---- F: projection + coalesced stores ----
    const int pg = tid & 31;              // float4 pixel group (32 x 4px)
    const int dg = tid >> 5;              // 16 dim groups x 48 dims
    const int prow = pg >> 3;             // 0..3
    const int pcol = pg & 7;              // 0..7

    float4 R = ((const float4*)spr)[pg];
    float4 G = ((const float4*)spg)[pg];
    float4 B = ((const float4*)spb)[pg];
    unsigned long long r01 = pk2(R.x, R.y), r23 = pk2(R.z, R.w);
    unsigned long long g01 = pk2(G.x, G.y), g23 = pk2(G.z, G.w);
    unsigned long long b01 = pk2(B.x, B.y), b23 = pk2(B.z, B.w);

    const int d0 = dg * 48;
    ulonglong2* outp = (ulonglong2*)(out + (size_t)d0 * PTOT
                                         + (size_t)(y0 + prow) * WW + x0) + pcol;

    #pragma unroll 8
    for (int k = 0; k < 48; k++) {
        ulonglong2 wa = sw2[d0 + k][0];   // {wr2, wg2}
        ulonglong2 wb = sw2[d0 + k][1];   // {wb2, bias2}
        ulonglong2 v;
        v.x = ffma2(b01, wb.x, ffma2(g01, wa.y, ffma2(r01, wa.x, wb.y)));
        v.y = ffma2(b23, wb.x, ffma2(g23, wa.y, ffma2(r23, wa.x, wb.y)));
        *outp = v;
        outp += PTOT / 4;                 // next dim (PTOT floats)
    }
}

// ============================================================
extern "C" void kernel_launch(void* const* d_in, const int* in_sizes, int n_in,
                              void* d_out, int out_size) {
    // metadata order: x, xyz, scaling, rotation, features, opacity, w_up, b_up
    const float* xyz      = (const float*)d_in[1];
    const float* scaling  = (const float*)d_in[2];
    const float* rotation = (const float*)d_in[3];
    const float* features = (const float*)d_in[4];
    const float* opacity  = (const float*)d_in[5];
    const float* w_up     = (const float*)d_in[6];
    const float* b_up     = (const float*)d_in[7];
    float* out = (float*)d_out;

    k_one<<<NBLK, NTHR>>>(xyz, scaling, rotation, features, opacity,
                          w_up, b_up, out);
}